// round 1
// baseline (speedup 1.0000x reference)
#include <cuda_runtime.h>
#include <cuda_bf16.h>
#include <cstdint>

// Problem constants
#define BATCH   2048
#define NTOK    64
#define DIM     256
#define HEADS   8
#define HEADDIM 32
#define MASK_NW 64

// Scratch for Q, K, V: [B, N, DIM] each (layout: row = b*64+i, col = h*32+d)
__device__ float g_Q[(size_t)BATCH * NTOK * DIM];
__device__ float g_K[(size_t)BATCH * NTOK * DIM];
__device__ float g_V[(size_t)BATCH * NTOK * DIM];

// ---------------------------------------------------------------------------
// Kernel 1: fused QKV projection GEMM.
//   out[m, n] = sum_k X[m,k] * W[n,k] + bias[n]
//   M = 131072, K = 256, N = 768 (q|k|v). blockIdx.x selects 128-col slab.
// 128x128x16 tiles, 256 threads, 8x8 micro-tile (split 4+4), reg prefetch.
// ---------------------------------------------------------------------------
__global__ __launch_bounds__(256) void qkv_gemm(
    const float* __restrict__ X,
    const float* __restrict__ Wq, const float* __restrict__ Bq,
    const float* __restrict__ Wk, const float* __restrict__ Bk,
    const float* __restrict__ Wv, const float* __restrict__ Bv)
{
    constexpr int BM = 128, BN = 128, BK = 16;
    constexpr int KTILES = DIM / BK;   // 16

    __shared__ float As[BK][BM];
    __shared__ float Bs[BK][BN];

    const int tid  = threadIdx.x;
    const int m0   = blockIdx.y * BM;
    const int nsel = blockIdx.x;       // 0..5

    const float* W;  const float* bias;  float* outp;
    if (nsel < 2)      { W = Wq; bias = Bq; outp = g_Q; }
    else if (nsel < 4) { W = Wk; bias = Bk; outp = g_K; }
    else               { W = Wv; bias = Bv; outp = g_V; }
    const int nl0 = (nsel & 1) * BN;   // 0 or 128 within the 256 output cols

    // Each thread loads 2 float4 for A and 2 for B per k-tile.
    // Tile = 128 rows x 16 floats = 512 float4; idx -> (row = idx>>2, c4 = (idx&3)*4)
    const int r0 = tid >> 2;
    const int c4 = (tid & 3) * 4;
    const int r1 = (tid + 256) >> 2;
    const int c4b = ((tid + 256) & 3) * 4;   // same as c4 actually (since 256%4==0) but keep general

    const int tx = tid & 15;   // col block
    const int ty = tid >> 4;   // row block

    float acc[8][8];
    #pragma unroll
    for (int i = 0; i < 8; i++)
        #pragma unroll
        for (int j = 0; j < 8; j++) acc[i][j] = 0.f;

    // prefetch registers
    float4 va0, va1, vb0, vb1;

    // load k-tile 0
    {
        const int kt = 0;
        va0 = *(const float4*)(X + (size_t)(m0 + r0) * DIM + kt * BK + c4);
        va1 = *(const float4*)(X + (size_t)(m0 + r1) * DIM + kt * BK + c4b);
        vb0 = *(const float4*)(W + (size_t)(nl0 + r0) * DIM + kt * BK + c4);
        vb1 = *(const float4*)(W + (size_t)(nl0 + r1) * DIM + kt * BK + c4b);
    }

    for (int kt = 0; kt < KTILES; kt++) {
        // regs -> smem (transposed)
        As[c4 + 0][r0] = va0.x;  As[c4 + 1][r0] = va0.y;
        As[c4 + 2][r0] = va0.z;  As[c4 + 3][r0] = va0.w;
        As[c4b + 0][r1] = va1.x; As[c4b + 1][r1] = va1.y;
        As[c4b + 2][r1] = va1.z; As[c4b + 3][r1] = va1.w;
        Bs[c4 + 0][r0] = vb0.x;  Bs[c4 + 1][r0] = vb0.y;
        Bs[c4 + 2][r0] = vb0.z;  Bs[c4 + 3][r0] = vb0.w;
        Bs[c4b + 0][r1] = vb1.x; Bs[c4b + 1][r1] = vb1.y;
        Bs[c4b + 2][r1] = vb1.z; Bs[c4b + 3][r1] = vb1.w;
        __syncthreads();

        // prefetch next tile
        if (kt + 1 < KTILES) {
            const int kn = kt + 1;
            va0 = *(const float4*)(X + (size_t)(m0 + r0) * DIM + kn * BK + c4);
            va1 = *(const float4*)(X + (size_t)(m0 + r1) * DIM + kn * BK + c4b);
            vb0 = *(const float4*)(W + (size_t)(nl0 + r0) * DIM + kn * BK + c4);
            vb1 = *(const float4*)(W + (size_t)(nl0 + r1) * DIM + kn * BK + c4b);
        }

        #pragma unroll
        for (int k = 0; k < BK; k++) {
            float4 a0 = *(const float4*)&As[k][ty * 4];
            float4 a1 = *(const float4*)&As[k][64 + ty * 4];
            float4 b0 = *(const float4*)&Bs[k][tx * 4];
            float4 b1 = *(const float4*)&Bs[k][64 + tx * 4];
            float ar[8] = {a0.x, a0.y, a0.z, a0.w, a1.x, a1.y, a1.z, a1.w};
            float br[8] = {b0.x, b0.y, b0.z, b0.w, b1.x, b1.y, b1.z, b1.w};
            #pragma unroll
            for (int i = 0; i < 8; i++)
                #pragma unroll
                for (int j = 0; j < 8; j++)
                    acc[i][j] += ar[i] * br[j];
        }
        __syncthreads();
    }

    // epilogue: add bias, store (float4 along cols)
    #pragma unroll
    for (int i = 0; i < 8; i++) {
        const int r = m0 + ((i < 4) ? (ty * 4 + i) : (64 + ty * 4 + (i - 4)));
        #pragma unroll
        for (int jh = 0; jh < 2; jh++) {
            const int c = (jh == 0) ? (tx * 4) : (64 + tx * 4);
            float4 v;
            v.x = acc[i][jh * 4 + 0] + bias[nl0 + c + 0];
            v.y = acc[i][jh * 4 + 1] + bias[nl0 + c + 1];
            v.z = acc[i][jh * 4 + 2] + bias[nl0 + c + 2];
            v.w = acc[i][jh * 4 + 3] + bias[nl0 + c + 3];
            *(float4*)(outp + (size_t)r * DIM + nl0 + c) = v;
        }
    }
}

// ---------------------------------------------------------------------------
// Kernel 2: fused windowed attention. One CTA per (window b, head h).
// ---------------------------------------------------------------------------
__global__ __launch_bounds__(256) void attn_kernel(
    const float* __restrict__ mask,        // [64, 64, 64]
    const float* __restrict__ bias_table,  // [225, 8]
    const int*   __restrict__ rel_index,   // [64, 64]
    float* __restrict__ out)               // [B, N, DIM]
{
    const int b = blockIdx.x;
    const int h = blockIdx.y;

    __shared__ float qs[64][33];
    __shared__ float ks[64][33];
    __shared__ float vs[64][36];   // padded so float4 rows stay 16B aligned
    __shared__ float sc[64][65];

    const int tid = threadIdx.x;

    // load q/k/v tiles [64 x 32] (coalesced: 32 threads per row)
    const size_t base = (size_t)b * (NTOK * DIM) + (size_t)h * HEADDIM;
    for (int i = tid; i < NTOK * HEADDIM; i += 256) {
        const int r = i >> 5, c = i & 31;
        const size_t g = base + (size_t)r * DIM + c;
        qs[r][c] = g_Q[g];
        ks[r][c] = g_K[g];
        vs[r][c] = g_V[g];
    }
    __syncthreads();

    // scores: 4x4 micro-tile per thread
    const int tr = (tid >> 4) * 4;    // row block (16 blocks x 4 = 64)
    const int tc = (tid & 15) * 4;    // col block
    {
        float acc[4][4] = {};
        #pragma unroll
        for (int k = 0; k < HEADDIM; k++) {
            float a[4], bb[4];
            #pragma unroll
            for (int i = 0; i < 4; i++) a[i] = qs[tr + i][k];
            #pragma unroll
            for (int j = 0; j < 4; j++) bb[j] = ks[tc + j][k];
            #pragma unroll
            for (int i = 0; i < 4; i++)
                #pragma unroll
                for (int j = 0; j < 4; j++)
                    acc[i][j] += a[i] * bb[j];
        }
        const float scale = 0.17677669529663687f;   // 1/sqrt(32)
        const float* mrow = mask + (size_t)(b & (MASK_NW - 1)) * (NTOK * NTOK);
        #pragma unroll
        for (int i = 0; i < 4; i++) {
            #pragma unroll
            for (int j = 0; j < 4; j++) {
                const int r = tr + i, c = tc + j;
                const int idx = r * NTOK + c;
                sc[r][c] = acc[i][j] * scale
                         + bias_table[rel_index[idx] * HEADS + h]
                         + mrow[idx];
            }
        }
    }
    __syncthreads();

    // softmax per row: 8 warps x 8 rows, 2 cols per lane
    {
        const int warp = tid >> 5, lane = tid & 31;
        for (int r = warp; r < NTOK; r += 8) {
            float v0 = sc[r][lane], v1 = sc[r][lane + 32];
            float m = fmaxf(v0, v1);
            #pragma unroll
            for (int o = 16; o; o >>= 1) m = fmaxf(m, __shfl_xor_sync(0xffffffffu, m, o));
            float e0 = __expf(v0 - m), e1 = __expf(v1 - m);
            float s = e0 + e1;
            #pragma unroll
            for (int o = 16; o; o >>= 1) s += __shfl_xor_sync(0xffffffffu, s, o);
            const float inv = 1.0f / s;
            sc[r][lane] = e0 * inv;
            sc[r][lane + 32] = e1 * inv;
        }
    }
    __syncthreads();

    // PV: out[r][d] = sum_c P[r][c] * V[c][d]; 2 rows x 4 d per thread
    {
        const int r2 = (tid >> 3) * 2;     // 32 row blocks x 2 = 64
        const int d4 = (tid & 7) * 4;      // 8 d blocks x 4 = 32
        float o00 = 0.f, o01 = 0.f, o02 = 0.f, o03 = 0.f;
        float o10 = 0.f, o11 = 0.f, o12 = 0.f, o13 = 0.f;
        #pragma unroll
        for (int c = 0; c < NTOK; c++) {
            const float4 v4 = *(const float4*)&vs[c][d4];
            const float p0 = sc[r2][c];
            const float p1 = sc[r2 + 1][c];
            o00 += p0 * v4.x; o01 += p0 * v4.y; o02 += p0 * v4.z; o03 += p0 * v4.w;
            o10 += p1 * v4.x; o11 += p1 * v4.y; o12 += p1 * v4.z; o13 += p1 * v4.w;
        }
        float* ob = out + (size_t)b * (NTOK * DIM) + (size_t)h * HEADDIM + d4;
        *(float4*)(ob + (size_t)r2 * DIM)       = make_float4(o00, o01, o02, o03);
        *(float4*)(ob + (size_t)(r2 + 1) * DIM) = make_float4(o10, o11, o12, o13);
    }
}

// ---------------------------------------------------------------------------
extern "C" void kernel_launch(void* const* d_in, const int* in_sizes, int n_in,
                              void* d_out, int out_size)
{
    const float* hs   = (const float*)d_in[0];  // [2048,64,256]
    const float* mask = (const float*)d_in[1];  // [64,64,64]
    const float* wq   = (const float*)d_in[2];
    const float* bq   = (const float*)d_in[3];
    const float* wk   = (const float*)d_in[4];
    const float* bk   = (const float*)d_in[5];
    const float* wv   = (const float*)d_in[6];
    const float* bv   = (const float*)d_in[7];
    const float* bt   = (const float*)d_in[8];  // [225,8]
    const int*   ri   = (const int*)d_in[9];    // [64,64]
    float* out = (float*)d_out;

    dim3 gemm_grid(6, (BATCH * NTOK) / 128);    // 6 x 1024
    qkv_gemm<<<gemm_grid, 256>>>(hs, wq, bq, wk, bk, wv, bv);

    dim3 attn_grid(BATCH, HEADS);               // 2048 x 8
    attn_kernel<<<attn_grid, 256>>>(mask, bt, ri, out);
}

// round 2
// speedup vs baseline: 2.3858x; 2.3858x over previous
#include <cuda_runtime.h>
#include <cstdint>

#define BATCH   2048
#define NTOK    64
#define DIM     256
#define HEADS   8
#define HEADDIM 32
#define MASK_NW 64

// Scratch: Q, K, V [B*N, DIM]; CMB = mask + gathered relative bias [w][h][64*64]
__device__ float g_Q[(size_t)BATCH * NTOK * DIM];
__device__ float g_K[(size_t)BATCH * NTOK * DIM];
__device__ float g_V[(size_t)BATCH * NTOK * DIM];
__device__ float g_CMB[(size_t)MASK_NW * HEADS * NTOK * NTOK];

__device__ __forceinline__ float f2tf32(float x) {
    float r;
    asm("cvt.rna.tf32.f32 %0, %1;" : "=f"(r) : "f"(x));
    return r;
}

__device__ __forceinline__ void mma8(float* d, const uint32_t* a, const uint32_t* b) {
    asm("mma.sync.aligned.m16n8k8.row.col.f32.tf32.tf32.f32 "
        "{%0,%1,%2,%3}, {%4,%5,%6,%7}, {%8,%9}, {%0,%1,%2,%3};"
        : "+f"(d[0]), "+f"(d[1]), "+f"(d[2]), "+f"(d[3])
        : "r"(a[0]), "r"(a[1]), "r"(a[2]), "r"(a[3]), "r"(b[0]), "r"(b[1]));
}

__device__ __forceinline__ uint32_t fbits(float x) { return __float_as_uint(x); }

// ---------------------------------------------------------------------------
// Kernel 0: precompute combined mask + relative-position bias.
//   g_CMB[(w*8 + h)*4096 + p] = mask[w*4096 + p] + bias_table[rel_index[p]*8 + h]
// ---------------------------------------------------------------------------
__global__ void prep_cmb(const float* __restrict__ mask,
                         const float* __restrict__ bt,
                         const int*   __restrict__ ri)
{
    const int idx = blockIdx.x * 256 + threadIdx.x;   // 2,097,152 total
    const int p = idx & 4095;
    const int h = (idx >> 12) & 7;
    const int w = idx >> 15;
    g_CMB[idx] = mask[w * 4096 + p] + bt[ri[p] * 8 + h];
}

// ---------------------------------------------------------------------------
// Kernel 1: fused QKV projection GEMM via tf32 mma.sync.
//   out[m, n] = sum_k X[m,k] * W[n,k] + bias[n]
//   M = 131072, K = 256. grid.x = 6 slabs of 128 output cols (q0 q1 k0 k1 v0 v1)
// CTA tile 128x128x32, 8 warps, warp tile 32x64, m16n8k8 tf32.
// ---------------------------------------------------------------------------
__global__ __launch_bounds__(256) void qkv_gemm_tc(
    const float* __restrict__ X,
    const float* __restrict__ Wq, const float* __restrict__ Bq,
    const float* __restrict__ Wk, const float* __restrict__ Bk,
    const float* __restrict__ Wv, const float* __restrict__ Bv)
{
    constexpr int BK = 32;
    constexpr int KTILES = DIM / BK;   // 8

    __shared__ float As[128][36];
    __shared__ float Bs[128][36];

    const int tid  = threadIdx.x;
    const int m0   = blockIdx.y * 128;
    const int nsel = blockIdx.x;       // 0..5

    const float* W; const float* bias; float* outp;
    if (nsel < 2)      { W = Wq; bias = Bq; outp = g_Q; }
    else if (nsel < 4) { W = Wk; bias = Bk; outp = g_K; }
    else               { W = Wv; bias = Bv; outp = g_V; }
    const int nl0 = (nsel & 1) * 128;

    const int lane = tid & 31;
    const int warp = tid >> 5;
    const int g  = lane >> 2;
    const int tg = lane & 3;
    const int wm = (warp >> 1) * 32;   // warp row offset in CTA tile
    const int wn = (warp & 1) * 64;    // warp col offset in CTA tile

    // global load mapping: thread handles 4 float4 within one row
    const int lrow = tid >> 1;          // 0..127
    const int lq   = (tid & 1) * 16;    // float offset 0 or 16

    float acc[2][8][4] = {};

    float4 va[4], vb[4];
    {
        const float* xa = X + (size_t)(m0 + lrow) * DIM + lq;
        const float* xb = W + (size_t)(nl0 + lrow) * DIM + lq;
        #pragma unroll
        for (int i = 0; i < 4; i++) {
            va[i] = *(const float4*)(xa + i * 4);
            vb[i] = *(const float4*)(xb + i * 4);
        }
    }

    for (int kt = 0; kt < KTILES; kt++) {
        #pragma unroll
        for (int i = 0; i < 4; i++) {
            const int c = lq + i * 4;
            As[lrow][c + 0] = f2tf32(va[i].x);
            As[lrow][c + 1] = f2tf32(va[i].y);
            As[lrow][c + 2] = f2tf32(va[i].z);
            As[lrow][c + 3] = f2tf32(va[i].w);
            Bs[lrow][c + 0] = f2tf32(vb[i].x);
            Bs[lrow][c + 1] = f2tf32(vb[i].y);
            Bs[lrow][c + 2] = f2tf32(vb[i].z);
            Bs[lrow][c + 3] = f2tf32(vb[i].w);
        }
        __syncthreads();

        if (kt + 1 < KTILES) {
            const float* xa = X + (size_t)(m0 + lrow) * DIM + (kt + 1) * BK + lq;
            const float* xb = W + (size_t)(nl0 + lrow) * DIM + (kt + 1) * BK + lq;
            #pragma unroll
            for (int i = 0; i < 4; i++) {
                va[i] = *(const float4*)(xa + i * 4);
                vb[i] = *(const float4*)(xb + i * 4);
            }
        }

        #pragma unroll
        for (int kc = 0; kc < BK; kc += 8) {
            uint32_t afr[2][4];
            #pragma unroll
            for (int mt = 0; mt < 2; mt++) {
                const int r = wm + mt * 16;
                afr[mt][0] = fbits(As[r + g    ][kc + tg]);
                afr[mt][1] = fbits(As[r + g + 8][kc + tg]);
                afr[mt][2] = fbits(As[r + g    ][kc + tg + 4]);
                afr[mt][3] = fbits(As[r + g + 8][kc + tg + 4]);
            }
            uint32_t bfr[8][2];
            #pragma unroll
            for (int nt = 0; nt < 8; nt++) {
                const int c = wn + nt * 8;
                bfr[nt][0] = fbits(Bs[c + g][kc + tg]);
                bfr[nt][1] = fbits(Bs[c + g][kc + tg + 4]);
            }
            #pragma unroll
            for (int mt = 0; mt < 2; mt++)
                #pragma unroll
                for (int nt = 0; nt < 8; nt++)
                    mma8(acc[mt][nt], afr[mt], bfr[nt]);
        }
        __syncthreads();
    }

    // epilogue: bias add + float2 stores
    #pragma unroll
    for (int nt = 0; nt < 8; nt++) {
        const int c = nl0 + wn + nt * 8 + tg * 2;
        const float b0 = bias[c], b1 = bias[c + 1];
        #pragma unroll
        for (int mt = 0; mt < 2; mt++) {
            const int r = m0 + wm + mt * 16 + g;
            float2 v0 = make_float2(acc[mt][nt][0] + b0, acc[mt][nt][1] + b1);
            float2 v1 = make_float2(acc[mt][nt][2] + b0, acc[mt][nt][3] + b1);
            *(float2*)(outp + (size_t)r * DIM + c)       = v0;
            *(float2*)(outp + (size_t)(r + 8) * DIM + c) = v1;
        }
    }
}

// ---------------------------------------------------------------------------
// Kernel 2: fused windowed attention via tf32 mma. One CTA = (window, head),
// 128 threads (4 warps). Warp w owns query rows [16w, 16w+16).
// ---------------------------------------------------------------------------
#define QS(r, c) sm_q[(r) * 36 + (c)]
#define KS(r, c) sm_k[(r) * 36 + (c)]
#define VS(r, c) sm_v[(r) * 40 + (c)]
#define SC(r, c) sm_s[(r) * 68 + (c)]

__global__ __launch_bounds__(128) void attn_tc(float* __restrict__ out)
{
    // pool: [0 .. 4608) q(2304)+k(2304), aliased by sc(4352) after scores
    //       [4608 .. 7168) v(2560)
    __shared__ float pool[7168];
    float* sm_q = pool;
    float* sm_k = pool + 2304;
    float* sm_s = pool;           // aliases q+k (dead after score mma)
    float* sm_v = pool + 4608;

    const int b = blockIdx.x;
    const int h = blockIdx.y;
    const int tid  = threadIdx.x;
    const int lane = tid & 31;
    const int warp = tid >> 5;
    const int g  = lane >> 2;
    const int tg = lane & 3;
    const int wm = warp * 16;

    // load q, k, v [64 x 32] with tf32 conversion
    const size_t gbase = ((size_t)b * NTOK) * DIM + (size_t)h * HEADDIM;
    #pragma unroll
    for (int i = 0; i < 4; i++) {
        const int f = tid + i * 128;
        const int r = f >> 3, c4 = (f & 7) * 4;
        const size_t go = gbase + (size_t)r * DIM + c4;
        float4 q4 = *(const float4*)(g_Q + go);
        float4 k4 = *(const float4*)(g_K + go);
        float4 v4 = *(const float4*)(g_V + go);
        QS(r, c4 + 0) = f2tf32(q4.x); QS(r, c4 + 1) = f2tf32(q4.y);
        QS(r, c4 + 2) = f2tf32(q4.z); QS(r, c4 + 3) = f2tf32(q4.w);
        KS(r, c4 + 0) = f2tf32(k4.x); KS(r, c4 + 1) = f2tf32(k4.y);
        KS(r, c4 + 2) = f2tf32(k4.z); KS(r, c4 + 3) = f2tf32(k4.w);
        VS(r, c4 + 0) = f2tf32(v4.x); VS(r, c4 + 1) = f2tf32(v4.y);
        VS(r, c4 + 2) = f2tf32(v4.z); VS(r, c4 + 3) = f2tf32(v4.w);
    }
    __syncthreads();

    // scores: warp computes rows [wm, wm+16) x 64 cols; S = Q K^T
    float sacc[8][4] = {};
    #pragma unroll
    for (int kc = 0; kc < HEADDIM; kc += 8) {
        uint32_t afr[4];
        afr[0] = fbits(QS(wm + g,     kc + tg));
        afr[1] = fbits(QS(wm + g + 8, kc + tg));
        afr[2] = fbits(QS(wm + g,     kc + tg + 4));
        afr[3] = fbits(QS(wm + g + 8, kc + tg + 4));
        #pragma unroll
        for (int nt = 0; nt < 8; nt++) {
            uint32_t bfr[2];
            bfr[0] = fbits(KS(nt * 8 + g, kc + tg));
            bfr[1] = fbits(KS(nt * 8 + g, kc + tg + 4));
            mma8(sacc[nt], afr, bfr);
        }
    }
    __syncthreads();   // all q/k fragment reads done before aliased sc stores

    // epilogue: scale + combined mask/bias, store fp32 scores
    {
        const float scale = 0.17677669529663687f;   // 1/sqrt(32)
        const float* cmb = g_CMB + (((size_t)(b & (MASK_NW - 1)) * HEADS + h) * (NTOK * NTOK));
        const int r0 = wm + g;
        #pragma unroll
        for (int nt = 0; nt < 8; nt++) {
            const int c0 = nt * 8 + tg * 2;
            float2 m0v = *(const float2*)(cmb + r0 * NTOK + c0);
            float2 m1v = *(const float2*)(cmb + (r0 + 8) * NTOK + c0);
            SC(r0,     c0)     = sacc[nt][0] * scale + m0v.x;
            SC(r0,     c0 + 1) = sacc[nt][1] * scale + m0v.y;
            SC(r0 + 8, c0)     = sacc[nt][2] * scale + m1v.x;
            SC(r0 + 8, c0 + 1) = sacc[nt][3] * scale + m1v.y;
        }
    }
    __syncwarp();

    // softmax over warp-owned rows; write P back as tf32
    #pragma unroll
    for (int rr = 0; rr < 16; rr++) {
        const int r = wm + rr;
        float v0 = SC(r, lane), v1 = SC(r, lane + 32);
        float m = fmaxf(v0, v1);
        #pragma unroll
        for (int o = 16; o; o >>= 1) m = fmaxf(m, __shfl_xor_sync(0xffffffffu, m, o));
        float e0 = __expf(v0 - m), e1 = __expf(v1 - m);
        float s = e0 + e1;
        #pragma unroll
        for (int o = 16; o; o >>= 1) s += __shfl_xor_sync(0xffffffffu, s, o);
        const float inv = 1.0f / s;
        SC(r, lane)      = f2tf32(e0 * inv);
        SC(r, lane + 32) = f2tf32(e1 * inv);
    }
    __syncwarp();

    // PV: O[wm..wm+16) x 32 = P(16x64) @ V(64x32)
    float oacc[4][4] = {};
    #pragma unroll
    for (int kc = 0; kc < NTOK; kc += 8) {
        uint32_t afr[4];
        afr[0] = fbits(SC(wm + g,     kc + tg));
        afr[1] = fbits(SC(wm + g + 8, kc + tg));
        afr[2] = fbits(SC(wm + g,     kc + tg + 4));
        afr[3] = fbits(SC(wm + g + 8, kc + tg + 4));
        #pragma unroll
        for (int nt = 0; nt < 4; nt++) {
            uint32_t bfr[2];
            bfr[0] = fbits(VS(kc + tg,     nt * 8 + g));
            bfr[1] = fbits(VS(kc + tg + 4, nt * 8 + g));
            mma8(oacc[nt], afr, bfr);
        }
    }

    // write output
    {
        float* ob = out + gbase;
        const int r0 = wm + g;
        #pragma unroll
        for (int nt = 0; nt < 4; nt++) {
            const int c0 = nt * 8 + tg * 2;
            *(float2*)(ob + (size_t)r0 * DIM + c0)       = make_float2(oacc[nt][0], oacc[nt][1]);
            *(float2*)(ob + (size_t)(r0 + 8) * DIM + c0) = make_float2(oacc[nt][2], oacc[nt][3]);
        }
    }
}

// ---------------------------------------------------------------------------
extern "C" void kernel_launch(void* const* d_in, const int* in_sizes, int n_in,
                              void* d_out, int out_size)
{
    const float* hs   = (const float*)d_in[0];
    const float* mask = (const float*)d_in[1];
    const float* wq   = (const float*)d_in[2];
    const float* bq   = (const float*)d_in[3];
    const float* wk   = (const float*)d_in[4];
    const float* bk   = (const float*)d_in[5];
    const float* wv   = (const float*)d_in[6];
    const float* bv   = (const float*)d_in[7];
    const float* bt   = (const float*)d_in[8];
    const int*   ri   = (const int*)d_in[9];
    float* out = (float*)d_out;

    prep_cmb<<<(MASK_NW * HEADS * NTOK * NTOK) / 256, 256>>>(mask, bt, ri);

    dim3 gemm_grid(6, (BATCH * NTOK) / 128);
    qkv_gemm_tc<<<gemm_grid, 256>>>(hs, wq, bq, wk, bk, wv, bv);

    dim3 attn_grid(BATCH, HEADS);
    attn_tc<<<attn_grid, 128>>>(out);
}